// round 1
// baseline (speedup 1.0000x reference)
#include <cuda_runtime.h>

// f32x2 packed-FMA helpers (PTX-only path; ptxas never auto-fuses to FFMA2)
#define FMA2(d, a, b, c) \
    asm("fma.rn.f32x2 %0, %1, %2, %3;" : "=l"(d) : "l"(a), "l"(b), "l"(c))
#define PACK2(d, lo, hi) \
    asm("mov.b64 %0, {%1, %2};" : "=l"(d) : "f"(lo), "f"(hi))
#define UNPACK2(lo, hi, d) \
    asm("mov.b64 {%0, %1}, %2;" : "=f"(lo), "=f"(hi) : "l"(d))

namespace cfg {
constexpr int H = 224, Wd = 224, C = 32, O = 32;
constexpr int TLW = 32, TLH = 8;       // output tile per block
constexpr int CCH = 16;                // channel chunk (matches mask checkpoint)
constexpr int TR = TLH + 2;            // 10 input rows per channel
constexpr int TC = TLW + 2;            // 34 input cols per channel
constexpr int S = 37;                  // smem row stride: bank = 5*row + 8*xb (conflict-free)
constexpr int WS_STRIDE = 33;          // weight smem stride: conflict-free staging writes
constexpr int WS_FLOATS = C * 9 * WS_STRIDE;      // 288*33 = 9504
constexpr int IN_FLOATS = CCH * TR * S;           // 16*10*37 = 5920
constexpr int SMEM_BYTES = (WS_FLOATS + IN_FLOATS) * 4;  // 61,696 B
}

__global__ __launch_bounds__(256, 2)
void conv_early_kernel(const float* __restrict__ x,
                       const float* __restrict__ W,
                       float* __restrict__ out)
{
    using namespace cfg;
    extern __shared__ float smem[];
    float* w_s  = smem;               // [k=c*9+dy*3+dx][o], stride 33
    float* in_s = smem + WS_FLOATS;   // [c][r][col], row stride 37

    const int tid = threadIdx.x;
    const int x0  = blockIdx.x * TLW;
    const int y0  = blockIdx.y * TLH;
    const int b   = blockIdx.z;

    // Stage weights: gmem W is [O][C][3][3]; consecutive idx -> smem offset +33
    // -> bank +1 (33 == 1 mod 32): conflict-free scatter.
    for (int idx = tid; idx < O * C * 9; idx += 256) {
        int o = idx / 288;
        int k = idx - o * 288;            // c*9 + dy*3 + dx
        w_s[k * WS_STRIDE + o] = W[idx];
    }

    // Thread decomposition: warp = one o-group (weight reads warp-uniform -> broadcast).
    const int og  = tid >> 5;             // 0..7 -> o = og*4 + 0..3
    const int pg  = tid & 31;
    const int row = pg >> 2;              // 0..7
    const int xb  = pg & 3;               // 0..3 -> x block of 8

    unsigned long long acc[16];           // acc[o*4+pp] = f32x2 for pixels (pp, pp+4)
    #pragma unroll
    for (int i = 0; i < 16; i++) acc[i] = 0ull;
    unsigned mask = 0;                    // early-terminate signs at the 16-channel checkpoint

    const float* xb_img = x + (size_t)b * C * H * Wd;

    for (int stage = 0; stage < 2; stage++) {
        if (stage) __syncthreads();       // protect in_s overwrite
        const int cbase = stage * CCH;

        // Cooperative input-tile load (16 ch x 10 rows x 34 cols), zero halo at edges.
        for (int idx = tid; idx < CCH * TR * TC; idx += 256) {
            int c   = idx / (TR * TC);
            int rem = idx - c * (TR * TC);
            int r   = rem / TC;
            int col = rem - r * TC;
            int gy = y0 - 1 + r;
            int gx = x0 - 1 + col;
            float v = 0.f;
            if ((unsigned)gy < (unsigned)H && (unsigned)gx < (unsigned)Wd)
                v = xb_img[((size_t)(cbase + c) * H + gy) * Wd + gx];
            in_s[(c * TR + r) * S + col] = v;
        }
        __syncthreads();

        const float* irow0 = in_s + row * S + xb * 8;
        const float* wb    = w_s + (cbase * 9) * WS_STRIDE + og * 4;

        #pragma unroll 2
        for (int c = 0; c < CCH; c++) {
            #pragma unroll
            for (int dy = 0; dy < 3; dy++) {
                const float* ir = irow0 + (c * TR + dy) * S;
                float v[10];
                #pragma unroll
                for (int i = 0; i < 10; i++) v[i] = ir[i];
                // pixel pairs (px, px+4): operand pair j serves px=pp, dx with pp+dx==j
                unsigned long long P[6];
                #pragma unroll
                for (int j = 0; j < 6; j++) PACK2(P[j], v[j], v[j + 4]);

                const float* wk = wb + (c * 9 + dy * 3) * WS_STRIDE;
                #pragma unroll
                for (int dx = 0; dx < 3; dx++) {
                    #pragma unroll
                    for (int o = 0; o < 4; o++) {
                        float w = wk[dx * WS_STRIDE + o];
                        unsigned long long wp;
                        PACK2(wp, w, w);
                        #pragma unroll
                        for (int pp = 0; pp < 4; pp++) {
                            FMA2(acc[o * 4 + pp], P[pp + dx], wp, acc[o * 4 + pp]);
                        }
                    }
                }
            }
        }

        if (stage == 0) {
            // Checkpoint: record sign of the 16-channel partial sum per output.
            #pragma unroll
            for (int i = 0; i < 16; i++) {
                float lo, hi;
                UNPACK2(lo, hi, acc[i]);
                mask |= (lo < 0.f ? 1u : 0u) << (2 * i);
                mask |= (hi < 0.f ? 1u : 0u) << (2 * i + 1);
            }
        }
    }

    // Epilogue: out = maskbit ? 0 : relu(full). float4 stores (x0+xb*8 is 32B aligned).
    const int gy  = y0 + row;
    const int gx0 = x0 + xb * 8;
    float* op = out + (((size_t)b * O + og * 4) * H + gy) * Wd + gx0;
    #pragma unroll
    for (int o = 0; o < 4; o++) {
        float lo[4], hi[4];
        #pragma unroll
        for (int pp = 0; pp < 4; pp++) {
            float l, h;
            UNPACK2(l, h, acc[o * 4 + pp]);
            int bi = 2 * (o * 4 + pp);
            l = ((mask >> bi) & 1u)       ? 0.f : fmaxf(l, 0.f);
            h = ((mask >> (bi + 1)) & 1u) ? 0.f : fmaxf(h, 0.f);
            lo[pp] = l;
            hi[pp] = h;
        }
        float4 a0 = make_float4(lo[0], lo[1], lo[2], lo[3]);   // px 0..3
        float4 a1 = make_float4(hi[0], hi[1], hi[2], hi[3]);   // px 4..7
        *reinterpret_cast<float4*>(op + (size_t)o * H * Wd)     = a0;
        *reinterpret_cast<float4*>(op + (size_t)o * H * Wd + 4) = a1;
    }
}

extern "C" void kernel_launch(void* const* d_in, const int* in_sizes, int n_in,
                              void* d_out, int out_size)
{
    using namespace cfg;
    const float* x = (const float*)d_in[0];   // [32][32][224][224] f32
    const float* W = (const float*)d_in[1];   // [32][32][3][3] f32
    float* out = (float*)d_out;               // [32][32][224][224] f32

    cudaFuncSetAttribute(conv_early_kernel,
                         cudaFuncAttributeMaxDynamicSharedMemorySize, SMEM_BYTES);
    dim3 grid(Wd / TLW, H / TLH, 32);         // 7 x 28 x 32 = 6272 blocks
    conv_early_kernel<<<grid, 256, SMEM_BYTES>>>(x, W, out);
}